// round 4
// baseline (speedup 1.0000x reference)
#include <cuda_runtime.h>
#include <cuda_bf16.h>
#include <math.h>

// Problem constants
#define NN    4096
#define DD    64
#define HH    4
#define OO    64
#define KK    2
#define KHT   8        // K*H
#define NUSER 4000
#define CC    2

// Device scratch (allocation-free rule: static __device__ arrays)
__device__ float g_hp [KHT * NN * OO];   // h_prime[kh][n][o]   (8 MB)
__device__ float g_att[KHT * NN * OO];   // attention output per (k,h)  (8 MB)
__device__ float g_thr [KHT * NN];       // -src[n]
__device__ float g_es1 [KHT * NN];       // exp(src)
__device__ float g_es2 [KHT * NN];       // exp(0.2*src)
__device__ float g_dstv[KHT * NN];       // dst[m]
__device__ float g_ed1 [KHT * NN];       // exp(dst)
__device__ float g_ed2 [KHT * NN];       // exp(0.2*dst)

// ---------------------------------------------------------------------------
// Kernel 1: h_prime[kh][n][o] = sum_d h[n][d] * w[kh][d][o]
// grid (N/64, KH), 256 threads. 64x64 output tile, 4x4 per thread.
// ---------------------------------------------------------------------------
__global__ void k_hproj(const float* __restrict__ h, const float* __restrict__ w) {
    const int kh = blockIdx.y;
    const int n0 = blockIdx.x * 64;
    __shared__ float shT[64][68];     // [d][i]  (transposed h tile)
    __shared__ float sw[64 * 64];     // [d][o]
    const int tid = threadIdx.x;

    // load w tile linearly (float4)
    const float4* wkh = (const float4*)(w + (size_t)kh * 64 * 64);
    #pragma unroll
    for (int it = 0; it < 4; it++) ((float4*)sw)[tid + it * 256] = wkh[tid + it * 256];

    // load h tile transposed: thread -> (d = tid&63, ig = tid>>6)
    {
        const int d = tid & 63, ig0 = tid >> 6;
        #pragma unroll
        for (int it = 0; it < 4; it++) {
            const int ig = ig0 + it * 4;
            float4 v;
            v.x = h[(size_t)(n0 + ig * 4 + 0) * DD + d];
            v.y = h[(size_t)(n0 + ig * 4 + 1) * DD + d];
            v.z = h[(size_t)(n0 + ig * 4 + 2) * DD + d];
            v.w = h[(size_t)(n0 + ig * 4 + 3) * DD + d];
            *(float4*)&shT[d][ig * 4] = v;
        }
    }
    __syncthreads();

    const int ty = tid >> 4, tx = tid & 15;
    float acc[4][4] = {};
    #pragma unroll 8
    for (int j = 0; j < 64; j++) {
        const float4 pv = *(const float4*)&shT[j][ty * 4];
        const float4 hv = *(const float4*)&sw[j * 64 + tx * 4];
        acc[0][0] += pv.x * hv.x; acc[0][1] += pv.x * hv.y; acc[0][2] += pv.x * hv.z; acc[0][3] += pv.x * hv.w;
        acc[1][0] += pv.y * hv.x; acc[1][1] += pv.y * hv.y; acc[1][2] += pv.y * hv.z; acc[1][3] += pv.y * hv.w;
        acc[2][0] += pv.z * hv.x; acc[2][1] += pv.z * hv.y; acc[2][2] += pv.z * hv.z; acc[2][3] += pv.z * hv.w;
        acc[3][0] += pv.w * hv.x; acc[3][1] += pv.w * hv.y; acc[3][2] += pv.w * hv.z; acc[3][3] += pv.w * hv.w;
    }
    float* hp = g_hp + (size_t)kh * NN * OO;
    #pragma unroll
    for (int r = 0; r < 4; r++) {
        float4 v = make_float4(acc[r][0], acc[r][1], acc[r][2], acc[r][3]);
        *(float4*)&hp[(size_t)(n0 + ty * 4 + r) * OO + tx * 4] = v;
    }
}

// ---------------------------------------------------------------------------
// Kernel 2: src/dst attention scalars + factorized exponentials.
// one warp per (kh, n).
// ---------------------------------------------------------------------------
__global__ void k_attvec(const float* __restrict__ a_src, const float* __restrict__ a_dst) {
    const int wg   = blockIdx.x * 8 + (threadIdx.x >> 5);
    const int lane = threadIdx.x & 31;
    const int kh = wg >> 12;          // / 4096
    const int n  = wg & (NN - 1);
    const float* hp = g_hp + ((size_t)kh * NN + n) * OO;
    const float t1 = tanhf(hp[lane]);
    const float t2 = tanhf(hp[lane + 32]);
    float as = t1 * a_src[kh * 64 + lane] + t2 * a_src[kh * 64 + lane + 32];
    float ad = t1 * a_dst[kh * 64 + lane] + t2 * a_dst[kh * 64 + lane + 32];
    #pragma unroll
    for (int off = 16; off; off >>= 1) {
        as += __shfl_xor_sync(0xFFFFFFFFu, as, off);
        ad += __shfl_xor_sync(0xFFFFFFFFu, ad, off);
    }
    if (lane == 0) {
        const int idx = kh * NN + n;
        g_thr [idx] = -as;
        g_es1 [idx] = expf(as);
        g_es2 [idx] = expf(0.2f * as);
        g_dstv[idx] = ad;
        g_ed1 [idx] = expf(ad);
        g_ed2 [idx] = expf(0.2f * ad);
    }
}

// ---------------------------------------------------------------------------
// Kernel 3 (dominant): out[n] = (sum_m P[n,m] * hp[m]) / (sum_m P[n,m])
//   P[n,m] = adj[k][n][m] * (dst[m] >= -src[n] ? es1[n]*ed1[m] : es2[n]*ed2[m])
// grid (N/64, KH), 256 threads. 64x64 output tile, m-tiles of 64.
// ---------------------------------------------------------------------------
__global__ void __launch_bounds__(256) k_main(const float* __restrict__ adj) {
    const int kh = blockIdx.y;
    const int k  = kh >> 2;           // / H
    const int n0 = blockIdx.x * 64;

    __shared__ float sPT[64][68];     // [j(m)][i(n)]  transposed P tile
    __shared__ float sH[64 * 64];     // [j(m)][o]
    __shared__ float sThr[64], sE1[64], sE2[64];
    __shared__ float sDen[64];

    const int tid = threadIdx.x;
    if (tid < 64) {
        const int idx = kh * NN + n0 + tid;
        sThr[tid] = g_thr[idx];
        sE1[tid]  = g_es1[idx];
        sE2[tid]  = g_es2[idx];
        sDen[tid] = 0.0f;
    }

    const int jj  = tid & 63;         // m within tile (fixed per thread)
    const int ig0 = tid >> 6;         // 0..3
    const int ty  = tid >> 4, tx = tid & 15;

    float acc[4][4] = {};
    float den[16]   = {};             // den[it*4+r] -> row (ig0+it*4)*4+r

    const float* __restrict__ adjk = adj + (size_t)k * NN * NN;
    const float* __restrict__ hpk  = g_hp  + (size_t)kh * NN * OO;
    const float* __restrict__ dstv = g_dstv + kh * NN;
    const float* __restrict__ ed1  = g_ed1  + kh * NN;
    const float* __restrict__ ed2  = g_ed2  + kh * NN;

    __syncthreads();

    for (int mt = 0; mt < NN; mt += 64) {
        // ---- load hp tile (64 x 64 floats) ----
        const float4* hpt = (const float4*)(hpk + (size_t)mt * OO);
        #pragma unroll
        for (int it = 0; it < 4; it++)
            ((float4*)sH)[tid + it * 256] = hpt[tid + it * 256];

        // ---- build P tile ----
        const int m  = mt + jj;
        const float dv = dstv[m];
        const float q1 = ed1[m];
        const float q2 = ed2[m];
        #pragma unroll
        for (int it = 0; it < 4; it++) {
            const int ig = ig0 + it * 4;
            float4 p;
            float* pp = &p.x;
            #pragma unroll
            for (int r = 0; r < 4; r++) {
                const int i = ig * 4 + r;
                const float a = adjk[(size_t)(n0 + i) * NN + m];
                const float e = (dv >= sThr[i]) ? sE1[i] * q1 : sE2[i] * q2;
                const float pv = a * e;
                pp[r] = pv;
                den[it * 4 + r] += pv;
            }
            *(float4*)&sPT[jj][ig * 4] = p;
        }
        __syncthreads();

        // ---- accumulate 4x4 per thread ----
        #pragma unroll 8
        for (int j = 0; j < 64; j++) {
            const float4 pv = *(const float4*)&sPT[j][ty * 4];
            const float4 hv = *(const float4*)&sH[j * 64 + tx * 4];
            acc[0][0] += pv.x * hv.x; acc[0][1] += pv.x * hv.y; acc[0][2] += pv.x * hv.z; acc[0][3] += pv.x * hv.w;
            acc[1][0] += pv.y * hv.x; acc[1][1] += pv.y * hv.y; acc[1][2] += pv.y * hv.z; acc[1][3] += pv.y * hv.w;
            acc[2][0] += pv.z * hv.x; acc[2][1] += pv.z * hv.y; acc[2][2] += pv.z * hv.z; acc[2][3] += pv.z * hv.w;
            acc[3][0] += pv.w * hv.x; acc[3][1] += pv.w * hv.y; acc[3][2] += pv.w * hv.z; acc[3][3] += pv.w * hv.w;
        }
        __syncthreads();
    }

    // ---- flush row denominators ----
    #pragma unroll
    for (int it = 0; it < 4; it++)
        #pragma unroll
        for (int r = 0; r < 4; r++)
            atomicAdd(&sDen[(ig0 + it * 4) * 4 + r], den[it * 4 + r]);
    __syncthreads();

    float* outp = g_att + (size_t)kh * NN * OO;
    #pragma unroll
    for (int r = 0; r < 4; r++) {
        const int i = ty * 4 + r;
        const float inv = 1.0f / sDen[i];
        float4 v = make_float4(acc[r][0] * inv, acc[r][1] * inv, acc[r][2] * inv, acc[r][3] * inv);
        *(float4*)&outp[(size_t)(n0 + i) * OO + tx * 4] = v;
    }
}

// ---------------------------------------------------------------------------
// Kernel 4: head-mean -> concat -> fc (C=2) -> log_softmax. One warp per row.
// ---------------------------------------------------------------------------
__global__ void k_final(const float* __restrict__ fc_w, const float* __restrict__ fc_b,
                        float* __restrict__ out) {
    const int wg = blockIdx.x * 8 + (threadIdx.x >> 5);
    if (wg >= NUSER) return;
    const int lane = threadIdx.x & 31;
    const int n = wg;

    float l0 = 0.0f, l1 = 0.0f;
    #pragma unroll
    for (int u = 0; u < 4; u++) {
        const int d = lane + u * 32;          // 0..127
        const int k = d >> 6, o = d & 63;
        float e = 0.0f;
        #pragma unroll
        for (int h = 0; h < HH; h++)
            e += g_att[(((size_t)(k * HH + h) * NN) + n) * OO + o];
        e *= 0.25f;
        l0 += e * fc_w[d];
        l1 += e * fc_w[128 + d];
    }
    #pragma unroll
    for (int off = 16; off; off >>= 1) {
        l0 += __shfl_xor_sync(0xFFFFFFFFu, l0, off);
        l1 += __shfl_xor_sync(0xFFFFFFFFu, l1, off);
    }
    if (lane == 0) {
        l0 += fc_b[0];
        l1 += fc_b[1];
        const float mx  = fmaxf(l0, l1);
        const float lse = mx + logf(expf(l0 - mx) + expf(l1 - mx));
        out[n * 2 + 0] = l0 - lse;
        out[n * 2 + 1] = l1 - lse;
    }
}

// ---------------------------------------------------------------------------
extern "C" void kernel_launch(void* const* d_in, const int* in_sizes, int n_in,
                              void* d_out, int out_size) {
    const float* h     = (const float*)d_in[0];
    const float* hadj  = (const float*)d_in[1];
    const float* w     = (const float*)d_in[2];
    const float* a_src = (const float*)d_in[3];
    const float* a_dst = (const float*)d_in[4];
    const float* fc_w  = (const float*)d_in[5];
    const float* fc_b  = (const float*)d_in[6];
    float* out = (float*)d_out;

    k_hproj <<<dim3(NN / 64, KHT), 256>>>(h, w);
    k_attvec<<<(KHT * NN) / 8, 256>>>(a_src, a_dst);
    k_main  <<<dim3(NN / 64, KHT), 256>>>(hadj);
    k_final <<<NUSER / 8, 256>>>(fc_w, fc_b, out);
}

// round 6
// speedup vs baseline: 4.0654x; 4.0654x over previous
#include <cuda_runtime.h>
#include <cuda_bf16.h>
#include <math.h>
#include <stdint.h>

// Problem constants
#define NN    4096
#define DD    64
#define HH    4
#define OO    64
#define KK    2
#define KHT   8        // K*H
#define NUSER 4000
#define CC    2

// Device scratch (allocation-free rule: static __device__ arrays)
__device__ float         g_hp [KHT * NN * OO];   // h_prime[kh][n][o]  fp32 (8 MB)
__device__ __nv_bfloat16 g_hpT[KHT * OO * NN];   // h_prime transposed [kh][o][m] bf16 (4 MB)
__device__ float         g_att[KHT * NN * OO];   // attention output per (k,h)  (8 MB)
__device__ float g_thr [KHT * NN];       // -src[n]
__device__ float g_es1 [KHT * NN];       // exp(src)
__device__ float g_es2 [KHT * NN];       // exp(0.2*src)
__device__ float g_dstv[KHT * NN];       // dst[m]
__device__ float g_ed1 [KHT * NN];       // exp(dst)
__device__ float g_ed2 [KHT * NN];       // exp(0.2*dst)

// ---------------------------------------------------------------------------
// Arch-agnostic tensor-core helpers (generic PTX, works on compute_103)
// ---------------------------------------------------------------------------
__device__ __forceinline__ uint32_t smem_u32(const void* p) {
    uint32_t a;
    asm("{ .reg .u64 t; cvta.to.shared.u64 t, %1; cvt.u32.u64 %0, t; }" : "=r"(a) : "l"(p));
    return a;
}
__device__ __forceinline__ void ldsm_x4(uint32_t* r, uint32_t addr) {
    asm volatile("ldmatrix.sync.aligned.m8n8.x4.shared.b16 {%0,%1,%2,%3}, [%4];"
        : "=r"(r[0]), "=r"(r[1]), "=r"(r[2]), "=r"(r[3]) : "r"(addr));
}
__device__ __forceinline__ void mma16816(float* c, const uint32_t* a, const uint32_t* b) {
    asm volatile("mma.sync.aligned.m16n8k16.row.col.f32.bf16.bf16.f32 "
        "{%0,%1,%2,%3}, {%4,%5,%6,%7}, {%8,%9}, {%0,%1,%2,%3};"
        : "+f"(c[0]), "+f"(c[1]), "+f"(c[2]), "+f"(c[3])
        : "r"(a[0]), "r"(a[1]), "r"(a[2]), "r"(a[3]), "r"(b[0]), "r"(b[1]));
}

// ---------------------------------------------------------------------------
// Kernel 1: h_prime = h @ w, plus bf16 transposed copy for the MMA B operand.
// grid (N/64, KH), 256 threads.
// ---------------------------------------------------------------------------
__global__ void k_hproj(const float* __restrict__ h, const float* __restrict__ w) {
    const int kh = blockIdx.y;
    const int n0 = blockIdx.x * 64;
    __shared__ float shT[64][68];     // [d][i]  (transposed h tile)
    __shared__ float buf[64 * 68];    // first 4096 floats: w tile; reused as [o][n] (stride 68)
    const int tid = threadIdx.x;

    const float4* wkh = (const float4*)(w + (size_t)kh * 64 * 64);
    #pragma unroll
    for (int it = 0; it < 4; it++) ((float4*)buf)[tid + it * 256] = wkh[tid + it * 256];

    {
        const int d = tid & 63, ig0 = tid >> 6;
        #pragma unroll
        for (int it = 0; it < 4; it++) {
            const int ig = ig0 + it * 4;
            float4 v;
            v.x = h[(size_t)(n0 + ig * 4 + 0) * DD + d];
            v.y = h[(size_t)(n0 + ig * 4 + 1) * DD + d];
            v.z = h[(size_t)(n0 + ig * 4 + 2) * DD + d];
            v.w = h[(size_t)(n0 + ig * 4 + 3) * DD + d];
            *(float4*)&shT[d][ig * 4] = v;
        }
    }
    __syncthreads();

    const int ty = tid >> 4, tx = tid & 15;
    float acc[4][4] = {};
    #pragma unroll 8
    for (int j = 0; j < 64; j++) {
        const float4 pv = *(const float4*)&shT[j][ty * 4];
        const float4 hv = *(const float4*)&buf[j * 64 + tx * 4];
        acc[0][0] += pv.x * hv.x; acc[0][1] += pv.x * hv.y; acc[0][2] += pv.x * hv.z; acc[0][3] += pv.x * hv.w;
        acc[1][0] += pv.y * hv.x; acc[1][1] += pv.y * hv.y; acc[1][2] += pv.y * hv.z; acc[1][3] += pv.y * hv.w;
        acc[2][0] += pv.z * hv.x; acc[2][1] += pv.z * hv.y; acc[2][2] += pv.z * hv.z; acc[2][3] += pv.z * hv.w;
        acc[3][0] += pv.w * hv.x; acc[3][1] += pv.w * hv.y; acc[3][2] += pv.w * hv.z; acc[3][3] += pv.w * hv.w;
    }
    // fp32 h_prime (for k_attvec)
    float* hp = g_hp + (size_t)kh * NN * OO;
    #pragma unroll
    for (int r = 0; r < 4; r++) {
        float4 v = make_float4(acc[r][0], acc[r][1], acc[r][2], acc[r][3]);
        *(float4*)&hp[(size_t)(n0 + ty * 4 + r) * OO + tx * 4] = v;
    }
    __syncthreads();            // done reading buf as w-tile
    // transpose into buf as [o][n_local], stride 68 to avoid conflicts
    #pragma unroll
    for (int r = 0; r < 4; r++)
        #pragma unroll
        for (int c = 0; c < 4; c++)
            buf[(tx * 4 + c) * 68 + ty * 4 + r] = acc[r][c];
    __syncthreads();
    // write bf16 transposed rows: thread -> row o = tid>>2, 16 n values
    {
        const int o = tid >> 2, nc = (tid & 3) * 16;
        __nv_bfloat162 tmp[8];
        #pragma unroll
        for (int j = 0; j < 8; j++)
            tmp[j] = __floats2bfloat162_rn(buf[o * 68 + nc + 2 * j], buf[o * 68 + nc + 2 * j + 1]);
        __nv_bfloat16* dst = g_hpT + ((size_t)kh * 64 + o) * NN + n0 + nc;
        *(uint4*)dst       = ((uint4*)tmp)[0];
        *(uint4*)(dst + 8) = ((uint4*)tmp)[1];
    }
}

// ---------------------------------------------------------------------------
// Kernel 2: src/dst attention scalars + factorized exponentials.
// ---------------------------------------------------------------------------
__global__ void k_attvec(const float* __restrict__ a_src, const float* __restrict__ a_dst) {
    const int wg   = blockIdx.x * 8 + (threadIdx.x >> 5);
    const int lane = threadIdx.x & 31;
    const int kh = wg >> 12;
    const int n  = wg & (NN - 1);
    const float* hp = g_hp + ((size_t)kh * NN + n) * OO;
    const float t1 = tanhf(hp[lane]);
    const float t2 = tanhf(hp[lane + 32]);
    float as = t1 * a_src[kh * 64 + lane] + t2 * a_src[kh * 64 + lane + 32];
    float ad = t1 * a_dst[kh * 64 + lane] + t2 * a_dst[kh * 64 + lane + 32];
    #pragma unroll
    for (int off = 16; off; off >>= 1) {
        as += __shfl_xor_sync(0xFFFFFFFFu, as, off);
        ad += __shfl_xor_sync(0xFFFFFFFFu, ad, off);
    }
    if (lane == 0) {
        const int idx = kh * NN + n;
        g_thr [idx] = -as;
        g_es1 [idx] = expf(as);
        g_es2 [idx] = expf(0.2f * as);
        g_dstv[idx] = ad;
        g_ed1 [idx] = expf(ad);
        g_ed2 [idx] = expf(0.2f * ad);
    }
}

// ---------------------------------------------------------------------------
// Kernel 3 (dominant, mma.sync bf16): for 2 heads of one k:
//   D[128,64] += P[128,64]_bf16 @ HpT[64(o),64(m)]_bf16^T   (chunks over m)
//   P[n,m] = adj[k][n][m] * (dst[m] >= -src[n] ? es1[n]*ed1[m] : es2[n]*ed2[m])
// grid (N/128=32, K=2, 2 head-pairs), 256 threads (8 warps), dynamic smem.
//
// smem (bytes from base):
//   P tiles : 2 heads x [128 rows x 72 bf16 (144B stride)] = 36864
//   B tiles : 2 heads x [ 64 rows x 72 bf16 (144B stride)] = 18432
//   m-vecs  : 2 x 3 x 64 floats                            =  1536
//   den     : 2 x 128 floats                               =  1024
// ---------------------------------------------------------------------------
#define P_OFF   0
#define PH_B    18432          // 128*144
#define B_OFF   36864
#define BH_B    9216           // 64*144
#define V_OFF   55296
#define D_OFF   56832
#define SMEM_DYN 57856

__global__ void __launch_bounds__(256) k_main3(const float* __restrict__ adj) {
    extern __shared__ char sm[];
    const uint32_t smb = smem_u32(sm);
    const int tid  = threadIdx.x;
    const int wid  = tid >> 5;
    const int lane = tid & 31;
    const int k    = blockIdx.y;
    const int z    = blockIdx.z;
    const int n0   = blockIdx.x * 128;
    const int kh0  = k * HH + z * 2;

    // ---- row-side (n) constants: thread pair (2*i, 2*i+1) owns row i ----
    const int i = tid >> 1;
    float thr[2], E1[2], E2[2];
    #pragma unroll
    for (int hh = 0; hh < 2; hh++) {
        const int idx = (kh0 + hh) * NN + n0 + i;
        thr[hh] = g_thr[idx]; E1[hh] = g_es1[idx]; E2[hh] = g_es2[idx];
    }
    const float* adjrow = adj + (size_t)k * NN * NN + (size_t)(n0 + i) * NN;
    const int mhalf = (tid & 1) * 32;

    // m-side vector staging mapping (threads < 96)
    const int smh = tid / 48, smr = tid % 48, smarr = smr >> 4, smf4 = smr & 15;

    // mma warp mapping: warp -> (head, 32-row slab)
    const int hw    = wid >> 2;
    const int mbase = (wid & 3) * 32;
    const int a_row = ((lane >> 3) & 1) * 8 + (lane & 7);
    const int a_k   = (lane >> 4) * 8;
    const uint32_t aAddr = smb + P_OFF + hw * PH_B + (mbase + a_row) * 144 + a_k * 2;
    const int b_n = ((lane >> 4) & 1) * 8 + (lane & 7);
    const int b_k = ((lane >> 3) & 1) * 8;
    const uint32_t bAddr = smb + B_OFF + hw * BH_B + b_n * 144 + b_k * 2;

    float acc[2][8][4];
    #pragma unroll
    for (int a = 0; a < 2; a++)
        #pragma unroll
        for (int b = 0; b < 8; b++)
            #pragma unroll
            for (int cc = 0; cc < 4; cc++) acc[a][b][cc] = 0.0f;
    float den[2] = {0.0f, 0.0f};

    for (int c = 0; c < NN / 64; c++) {
        const int mt = c << 6;
        // ---- prefetch gmem to registers ----
        float4 a4[8];
        #pragma unroll
        for (int r = 0; r < 8; r++)
            a4[r] = *(const float4*)(adjrow + mt + mhalf + r * 4);
        uint4 b4[4];
        int brow[4], bcol[4], bhead[4];
        #pragma unroll
        for (int it = 0; it < 4; it++) {
            const int idx = tid + it * 256;
            bhead[it] = idx >> 9;
            const int rem = idx & 511;
            brow[it] = rem >> 3; bcol[it] = rem & 7;
            b4[it] = *(const uint4*)(g_hpT + ((size_t)(kh0 + bhead[it]) * 64 + brow[it]) * NN + mt + bcol[it] * 8);
        }
        float4 mv;
        if (tid < 96) {
            const float* src = (smarr == 0 ? g_dstv : (smarr == 1 ? g_ed1 : g_ed2))
                               + (kh0 + smh) * NN + mt + smf4 * 4;
            mv = *(const float4*)src;
        }
        __syncthreads();   // prior chunk's ldmatrix reads complete
        // ---- stage smem ----
        if (tid < 96)
            *(float4*)(sm + V_OFF + (smh * 3 + smarr) * 256 + smf4 * 16) = mv;
        #pragma unroll
        for (int it = 0; it < 4; it++)
            *(uint4*)(sm + B_OFF + bhead[it] * BH_B + brow[it] * 144 + bcol[it] * 16) = b4[it];
        __syncthreads();   // m-vectors visible to all
        // ---- build P tiles (bf16) + accumulate denominators ----
        #pragma unroll
        for (int hh = 0; hh < 2; hh++) {
            const float* sdv = (const float*)(sm + V_OFF + (hh * 3 + 0) * 256);
            const float* sq1 = (const float*)(sm + V_OFF + (hh * 3 + 1) * 256);
            const float* sq2 = (const float*)(sm + V_OFF + (hh * 3 + 2) * 256);
            const float t = thr[hh], e1 = E1[hh], e2 = E2[hh];
            float d0 = 0.0f;
            #pragma unroll
            for (int r = 0; r < 8; r++) {
                const int ml = mhalf + r * 4;
                const float4 dv = *(const float4*)(sdv + ml);
                const float4 q1 = *(const float4*)(sq1 + ml);
                const float4 q2 = *(const float4*)(sq2 + ml);
                const float p0 = a4[r].x * ((dv.x >= t) ? e1 * q1.x : e2 * q2.x);
                const float p1 = a4[r].y * ((dv.y >= t) ? e1 * q1.y : e2 * q2.y);
                const float p2 = a4[r].z * ((dv.z >= t) ? e1 * q1.z : e2 * q2.z);
                const float p3 = a4[r].w * ((dv.w >= t) ? e1 * q1.w : e2 * q2.w);
                d0 += (p0 + p1) + (p2 + p3);
                __nv_bfloat162 lo = __floats2bfloat162_rn(p0, p1);
                __nv_bfloat162 hi = __floats2bfloat162_rn(p2, p3);
                uint2 v;
                v.x = *(uint32_t*)&lo;
                v.y = *(uint32_t*)&hi;
                *(uint2*)(sm + P_OFF + hh * PH_B + i * 144 + ml * 2) = v;
            }
            den[hh] += d0;
        }
        __syncthreads();   // P + B tiles visible
        // ---- tensor cores: 64 x m16n8k16 per warp ----
        #pragma unroll
        for (int ks = 0; ks < 4; ks++) {
            uint32_t af0[4], af1[4];
            ldsm_x4(af0, aAddr + ks * 32);
            ldsm_x4(af1, aAddr + 16 * 144 + ks * 32);
            #pragma unroll
            for (int nt = 0; nt < 4; nt++) {
                uint32_t bf[4];
                ldsm_x4(bf, bAddr + nt * (16 * 144) + ks * 32);
                mma16816(acc[0][2 * nt],     af0, bf);
                mma16816(acc[0][2 * nt + 1], af0, bf + 2);
                mma16816(acc[1][2 * nt],     af1, bf);
                mma16816(acc[1][2 * nt + 1], af1, bf + 2);
            }
        }
    }

    // ---- denominator reduce: pairs (tid, tid^1) share row i ----
    float ds0 = den[0] + __shfl_xor_sync(0xFFFFFFFFu, den[0], 1);
    float ds1 = den[1] + __shfl_xor_sync(0xFFFFFFFFu, den[1], 1);
    if ((tid & 1) == 0) {
        ((float*)(sm + D_OFF))[i]       = ds0;
        ((float*)(sm + D_OFF))[128 + i] = ds1;
    }
    __syncthreads();

    // ---- epilogue: scale by 1/den, store ----
    const float* sden = (const float*)(sm + D_OFF) + hw * 128;
    #pragma unroll
    for (int mt2 = 0; mt2 < 2; mt2++) {
        const int row0 = mbase + mt2 * 16 + (lane >> 2);
        const float inv0 = 1.0f / sden[row0];
        const float inv1 = 1.0f / sden[row0 + 8];
        float* op0 = g_att + ((size_t)(kh0 + hw) * NN + n0 + row0) * OO;
        float* op1 = op0 + 8 * OO;
        #pragma unroll
        for (int j = 0; j < 8; j++) {
            const int col = j * 8 + (lane & 3) * 2;
            float2 v0 = make_float2(acc[mt2][j][0] * inv0, acc[mt2][j][1] * inv0);
            float2 v1 = make_float2(acc[mt2][j][2] * inv1, acc[mt2][j][3] * inv1);
            *(float2*)(op0 + col) = v0;
            *(float2*)(op1 + col) = v1;
        }
    }
}

// ---------------------------------------------------------------------------
// Kernel 4: head-mean -> concat -> fc (C=2) -> log_softmax.
// ---------------------------------------------------------------------------
__global__ void k_final(const float* __restrict__ fc_w, const float* __restrict__ fc_b,
                        float* __restrict__ out) {
    const int wg = blockIdx.x * 8 + (threadIdx.x >> 5);
    if (wg >= NUSER) return;
    const int lane = threadIdx.x & 31;
    const int n = wg;

    float l0 = 0.0f, l1 = 0.0f;
    #pragma unroll
    for (int u = 0; u < 4; u++) {
        const int d = lane + u * 32;
        const int k = d >> 6, o = d & 63;
        float e = 0.0f;
        #pragma unroll
        for (int h = 0; h < HH; h++)
            e += g_att[(((size_t)(k * HH + h) * NN) + n) * OO + o];
        e *= 0.25f;
        l0 += e * fc_w[d];
        l1 += e * fc_w[128 + d];
    }
    #pragma unroll
    for (int off = 16; off; off >>= 1) {
        l0 += __shfl_xor_sync(0xFFFFFFFFu, l0, off);
        l1 += __shfl_xor_sync(0xFFFFFFFFu, l1, off);
    }
    if (lane == 0) {
        l0 += fc_b[0];
        l1 += fc_b[1];
        const float mx  = fmaxf(l0, l1);
        const float lse = mx + logf(expf(l0 - mx) + expf(l1 - mx));
        out[n * 2 + 0] = l0 - lse;
        out[n * 2 + 1] = l1 - lse;
    }
}

// ---------------------------------------------------------------------------
extern "C" void kernel_launch(void* const* d_in, const int* in_sizes, int n_in,
                              void* d_out, int out_size) {
    (void)in_sizes; (void)n_in; (void)out_size;
    const float* h     = (const float*)d_in[0];
    const float* hadj  = (const float*)d_in[1];
    const float* w     = (const float*)d_in[2];
    const float* a_src = (const float*)d_in[3];
    const float* a_dst = (const float*)d_in[4];
    const float* fc_w  = (const float*)d_in[5];
    const float* fc_b  = (const float*)d_in[6];
    float* out = (float*)d_out;

    static int smem_set = 0;
    if (!smem_set) {
        cudaFuncSetAttribute(k_main3, cudaFuncAttributeMaxDynamicSharedMemorySize, SMEM_DYN);
        smem_set = 1;
    }

    k_hproj <<<dim3(NN / 64, KHT), 256>>>(h, w);
    k_attvec<<<(KHT * NN) / 8, 256>>>(a_src, a_dst);
    k_main3 <<<dim3(NN / 128, KK, 2), 256, SMEM_DYN>>>(hadj);
    k_final <<<NUSER / 8, 256>>>(fc_w, fc_b, out);
}